// round 9
// baseline (speedup 1.0000x reference)
#include <cuda_runtime.h>
#include <cuda_bf16.h>
#include <cstdint>

// Problem constants (fixed shapes)
#define B_SZ   256
#define T_SZ   512
#define EMB    128
#define HID    256
#define NCLS   32000

// GEMM tiling
#define BM      256
#define BN      128
#define ASTR    264              // A_s row stride in bf16 (528B = 33*16)
#define CHUNK_K 32
#define NCHUNK  (HID / CHUNK_K)  // 8
#define NBUF    4
#define BSTR    40               // B_s row stride in fp32 (160B = 10*16)
#define BBUF    (BN * BSTR)      // one B buffer, floats (5120)
#define GRID    148
#define NTILES  (NCLS / BN)      // 250
#define ESTR    130              // E_s row stride in fp32 (520B, 8B aligned)

// Scratch + barrier state (zero-initialized; kernel self-resets each run)
__device__ __nv_bfloat16 g_h0[B_SZ * HID];
__device__ unsigned g_arrive;
__device__ unsigned g_done;

__device__ __forceinline__ void cp16(void* dst_smem, const void* src) {
    uint32_t d = (uint32_t)__cvta_generic_to_shared(dst_smem);
    asm volatile("cp.async.cg.shared.global [%0], [%1], 16;" :: "r"(d), "l"(src));
}
__device__ __forceinline__ void cp_commit() {
    asm volatile("cp.async.commit_group;" ::: "memory");
}
__device__ __forceinline__ void cp_wait2() {
    asm volatile("cp.async.wait_group 2;" ::: "memory");
}

// Issue one B chunk (CHUNK_K=32 fp32 cols x 128 rows) into buffer `dst`.
__device__ __forceinline__ void issue_b_chunk(
    float* dst, const float* __restrict__ W_w, int n0, int ck, int tid)
{
#pragma unroll
    for (int k = 0; k < 2; k++) {
        int idx = tid + k * 512;           // 1024 segs (128 rows x 8 segs)
        int row = idx >> 3;
        int seg = idx & 7;                 // 8 segs * 16B = 128B = 32 floats
        cp16(dst + row * BSTR + seg * 4,
             W_w + (size_t)(n0 + row) * HID + ck * CHUNK_K + seg * 4);
    }
}

// ---------------------------------------------------------------------------
// ONE fused kernel: LSTM h0 (phase 1) -> device barrier -> logits GEMM
// (phase 2, the validated R6 4-buffer cp.async pipeline, persistent tiles).
// ---------------------------------------------------------------------------
__global__ void __launch_bounds__(512, 1) fused_kernel(
    const int* __restrict__ X, const float* __restrict__ C_table,
    const float* __restrict__ U_i, const float* __restrict__ b_i,
    const float* __restrict__ U_c, const float* __restrict__ b_c,
    const float* __restrict__ U_o, const float* __restrict__ b_o,
    const float* __restrict__ W_w, const float* __restrict__ b_out,
    float* __restrict__ out)
{
    extern __shared__ char smem_raw[];
    __nv_bfloat16* A_s = (__nv_bfloat16*)smem_raw;              // [256][ASTR]
    float*         B_s = (float*)(smem_raw + BM * ASTR * 2);    // 4*[128][BSTR]
    float*         E_s = (float*)smem_raw;  // phase-1 overlay [256][ESTR]

    const int tid = threadIdx.x;
    const int bid = blockIdx.x;

    // ================= Phase 1: h0 (CTAs 0..127; h pair = 2*bid) ===========
    if (bid < 128) {
        // Preload E[b][:] = C_table[X[b, T-1]] into E_s (coalesced float2)
        {
            int row  = tid >> 1;
            int part = tid & 1;
            int tok  = X[row * T_SZ + (T_SZ - 1)];
            const float2* src = (const float2*)(C_table + (size_t)tok * EMB + part * 64);
            float2* dst = (float2*)(E_s + row * ESTR + part * 64);
#pragma unroll
            for (int j = 0; j < 32; j++) dst[j] = src[j];
        }
        __syncthreads();

        const int b = tid >> 1;
        const int h = 2 * bid + (tid & 1);
        float ai = b_i[h], ag = b_c[h], ao = b_o[h];
        const float* Eb = E_s + b * ESTR;
#pragma unroll 4
        for (int e = 0; e < EMB; e++) {
            float ev = Eb[e];
            ai = fmaf(ev, U_i[e * HID + h], ai);   // warp-broadcast loads
            ag = fmaf(ev, U_c[e * HID + h], ag);
            ao = fmaf(ev, U_o[e * HID + h], ao);
        }
        float i0 = 1.0f / (1.0f + __expf(-ai));
        float g0 = tanhf(ag);
        float o0 = 1.0f / (1.0f + __expf(-ao));
        g_h0[b * HID + h] = __float2bfloat16(o0 * tanhf(i0 * g0));
    }

    // ================= Device-wide barrier (all 148 CTAs co-resident) ======
    __threadfence();     // publish this thread's g_h0 writes
    __syncthreads();     // all threads of CTA done + fenced
    if (tid == 0) {
        atomicAdd(&g_arrive, 1u);
        unsigned v; long it = 0;
        do {
            asm volatile("ld.acquire.gpu.u32 %0, [%1];" : "=r"(v) : "l"(&g_arrive));
        } while (v < GRID && ++it < 200000000L);   // cap: never hang the bench
    }
    __syncthreads();     // release whole CTA; acquire in tid0 orders g_h0 reads

    // ================= Phase 2: logits GEMM (persistent tiles) =============
    // Issue A load once per CTA: all of g_h0 (128KB) in 16B segments.
    {
        const char* src = (const char*)g_h0;
#pragma unroll
        for (int k = 0; k < 16; k++) {
            int idx = tid + k * 512;       // 8192 segs (256 rows x 32 segs)
            int row = idx >> 5;
            int seg = idx & 31;
            cp16((char*)A_s + row * (ASTR * 2) + seg * 16,
                 src + row * (HID * 2) + seg * 16);
        }
    }
    // (A joins the first tile's chunk-0 commit group below)

    const int wid  = tid >> 5;
    const int lane = tid & 31;
    const int wm   = wid >> 2;      // 0..3 -> M offset wm*64
    const int wn   = wid & 3;       // 0..3 -> N offset wn*32
    const int gr   = lane >> 2;
    const int tig  = lane & 3;
    const int lm_row = (lane & 15);
    const int lm_col = ((lane >> 4) & 1) << 3;

    for (int tile = bid; tile < NTILES; tile += GRID) {
        const int n0 = tile * BN;

        // prologue: chunks 0,1,2 (chunk0's group includes A on first tile)
        issue_b_chunk(B_s + 0 * BBUF, W_w, n0, 0, tid); cp_commit();
        issue_b_chunk(B_s + 1 * BBUF, W_w, n0, 1, tid); cp_commit();
        issue_b_chunk(B_s + 2 * BBUF, W_w, n0, 2, tid); cp_commit();

        float acc[4][4][4];
#pragma unroll
        for (int mi = 0; mi < 4; mi++)
#pragma unroll
            for (int ni = 0; ni < 4; ni++)
#pragma unroll
                for (int r = 0; r < 4; r++) acc[mi][ni][r] = 0.0f;

#pragma unroll
        for (int c = 0; c < NCHUNK; c++) {
            cp_wait2();        // chunk c (and A on very first iter) complete
            __syncthreads();

            const float* Bb = B_s + (c & 3) * BBUF;
#pragma unroll
            for (int kkl = 0; kkl < CHUNK_K / 16; kkl++) {
                const int kbg = c * CHUNK_K + kkl * 16;
                const int kbl = kkl * 16;
                uint32_t a[4][4];
#pragma unroll
                for (int mi = 0; mi < 4; mi++) {
                    uint32_t addr = (uint32_t)__cvta_generic_to_shared(
                        &A_s[(wm * 64 + mi * 16 + lm_row) * ASTR + kbg + lm_col]);
                    asm volatile(
                        "ldmatrix.sync.aligned.m8n8.x4.shared.b16 {%0,%1,%2,%3}, [%4];"
                        : "=r"(a[mi][0]), "=r"(a[mi][1]), "=r"(a[mi][2]), "=r"(a[mi][3])
                        : "r"(addr));
                }
                uint32_t bf[4][2];
#pragma unroll
                for (int ni = 0; ni < 4; ni++) {
                    const float* p =
                        Bb + (wn * 32 + ni * 8 + gr) * BSTR + kbl + tig * 2;
                    float2 f0 = *(const float2*)(p);
                    float2 f1 = *(const float2*)(p + 8);
                    __nv_bfloat162 p0 = __floats2bfloat162_rn(f0.x, f0.y);
                    __nv_bfloat162 p1 = __floats2bfloat162_rn(f1.x, f1.y);
                    bf[ni][0] = *(const uint32_t*)&p0;
                    bf[ni][1] = *(const uint32_t*)&p1;
                }
#pragma unroll
                for (int mi = 0; mi < 4; mi++) {
#pragma unroll
                    for (int ni = 0; ni < 4; ni++) {
                        asm volatile(
                            "mma.sync.aligned.m16n8k16.row.col.f32.bf16.bf16.f32 "
                            "{%0,%1,%2,%3}, {%4,%5,%6,%7}, {%8,%9}, {%0,%1,%2,%3};"
                            : "+f"(acc[mi][ni][0]), "+f"(acc[mi][ni][1]),
                              "+f"(acc[mi][ni][2]), "+f"(acc[mi][ni][3])
                            : "r"(a[mi][0]), "r"(a[mi][1]), "r"(a[mi][2]), "r"(a[mi][3]),
                              "r"(bf[ni][0]), "r"(bf[ni][1]));
                    }
                }
            }
            __syncthreads();   // all reads of buf c&3 done before refill

            if (c + 3 < NCHUNK)
                issue_b_chunk(B_s + ((c + 3) & 3) * BBUF, W_w, n0, c + 3, tid);
            cp_commit();       // unconditional: exact group numbering
        }

        // epilogue: add b_out, fp32 float2 stores
        float bo0[4], bo1[4];
#pragma unroll
        for (int ni = 0; ni < 4; ni++) {
            int col = n0 + wn * 32 + ni * 8 + tig * 2;
            bo0[ni] = b_out[col];
            bo1[ni] = b_out[col + 1];
        }
#pragma unroll
        for (int mi = 0; mi < 4; mi++) {
            int row = wm * 64 + mi * 16 + gr;
#pragma unroll
            for (int ni = 0; ni < 4; ni++) {
                int col = n0 + wn * 32 + ni * 8 + tig * 2;
                float2 v0 = make_float2(acc[mi][ni][0] + bo0[ni],
                                        acc[mi][ni][1] + bo1[ni]);
                float2 v1 = make_float2(acc[mi][ni][2] + bo0[ni],
                                        acc[mi][ni][3] + bo1[ni]);
                *(float2*)(&out[(size_t)row * NCLS + col])       = v0;
                *(float2*)(&out[(size_t)(row + 8) * NCLS + col]) = v1;
            }
        }
    }

    // ================= Barrier state reset (deterministic replays) =========
    __syncthreads();
    if (tid == 0) {
        unsigned d = atomicAdd(&g_done, 1u);
        if (d == GRID - 1) {   // last CTA: everyone else is past the spin
            g_arrive = 0;
            g_done   = 0;
        }
    }
}

// ---------------------------------------------------------------------------
// Launcher — ONE graph node.
// Input order: 0=X 1=C_table 2=U_i 3=V_i 4=b_i 5=U_f 6=V_f 7=b_f
//  8=U_c 9=V_c 10=b_c 11=U_o 12=V_o 13=b_o 14..25=layer1 (unused) 26=W_w 27=b_out
// ---------------------------------------------------------------------------
extern "C" void kernel_launch(void* const* d_in, const int* in_sizes, int n_in,
                              void* d_out, int out_size)
{
    const int*   X       = (const int*)d_in[0];
    const float* C_table = (const float*)d_in[1];
    const float* U_i     = (const float*)d_in[2];
    const float* b_i     = (const float*)d_in[4];
    const float* U_c     = (const float*)d_in[8];
    const float* b_c     = (const float*)d_in[10];
    const float* U_o     = (const float*)d_in[11];
    const float* b_o     = (const float*)d_in[13];
    const float* W_w     = (const float*)d_in[26];
    const float* b_out   = (const float*)d_in[27];
    float* out = (float*)d_out;

    const int smem_bytes = BM * ASTR * 2 + NBUF * BBUF * (int)sizeof(float); // 217088
    cudaFuncSetAttribute(fused_kernel,
                         cudaFuncAttributeMaxDynamicSharedMemorySize, smem_bytes);
    fused_kernel<<<GRID, 512, smem_bytes>>>(X, C_table, U_i, b_i, U_c, b_c,
                                            U_o, b_o, W_w, b_out, out);
}

// round 11
// speedup vs baseline: 1.3253x; 1.3253x over previous
#include <cuda_runtime.h>
#include <cuda_bf16.h>
#include <cstdint>

// Problem constants (fixed shapes)
#define B_SZ   256
#define T_SZ   512
#define EMB    128
#define HID    256
#define NCLS   32000

// Scratch: h0 at last timestep, stored bf16 for tensor-core GEMM
__device__ __nv_bfloat16 g_h0[B_SZ * HID];

// ---------------------------------------------------------------------------
// Kernel 1: h0_last[b, h] for the 256 last-timestep tokens. (validated)
// ---------------------------------------------------------------------------
__global__ void __launch_bounds__(256) lstm_h0_kernel(
    const int* __restrict__ X, const float* __restrict__ C_table,
    const float* __restrict__ U_i, const float* __restrict__ b_i,
    const float* __restrict__ U_c, const float* __restrict__ b_c,
    const float* __restrict__ U_o, const float* __restrict__ b_o)
{
    __shared__ float E_s[8][EMB];
    const int tid = threadIdx.x;
    const int b0  = blockIdx.y * 8;

    for (int i = tid; i < 8 * EMB; i += 256) {
        int b = i >> 7;
        int e = i & (EMB - 1);
        int tok = X[(b0 + b) * T_SZ + (T_SZ - 1)];
        E_s[b][e] = C_table[tok * EMB + e];
    }
    __syncthreads();

    const int h    = blockIdx.x * 64 + (tid & 63);
    const int bsub = tid >> 6;
    const int r0   = bsub * 2;

    float ai[2], ag[2], ao[2];
    const float bi = b_i[h], bc = b_c[h], bo = b_o[h];
#pragma unroll
    for (int r = 0; r < 2; r++) { ai[r] = bi; ag[r] = bc; ao[r] = bo; }

#pragma unroll 4
    for (int e = 0; e < EMB; e++) {
        float ui = U_i[e * HID + h];
        float uc = U_c[e * HID + h];
        float uo = U_o[e * HID + h];
#pragma unroll
        for (int r = 0; r < 2; r++) {
            float ev = E_s[r0 + r][e];
            ai[r] = fmaf(ev, ui, ai[r]);
            ag[r] = fmaf(ev, uc, ag[r]);
            ao[r] = fmaf(ev, uo, ao[r]);
        }
    }

#pragma unroll
    for (int r = 0; r < 2; r++) {
        float i0 = 1.0f / (1.0f + __expf(-ai[r]));
        float g0 = tanhf(ag[r]);
        float o0 = 1.0f / (1.0f + __expf(-ao[r]));
        float c0 = i0 * g0;
        float h0 = o0 * tanhf(c0);
        g_h0[(b0 + r0 + r) * HID + h] = __float2bfloat16(h0);
    }
}

// ---------------------------------------------------------------------------
// Kernel 2: logits[256, 32000] = h0[256,256] @ W_w[32000,256]^T + b_out
// Balanced persistent bf16 mma.sync GEMM, continuous cp.async stream.
//   GRID = 125 CTAs x 512 thr; each CTA does EXACTLY 2 tiles (bid, bid+125)
//   of M=256 x N=128 -> perfect balance, A (h0) loaded once per CTA.
//   16 flat chunk phases (8 per tile), CHUNK_K=32, 4 buffers, wait_group 2;
//   the stream never drains at the tile boundary; tile-0 epilogue overlaps
//   tile-1's in-flight loads. ONE __syncthreads per phase.
// ---------------------------------------------------------------------------
#define BM      256
#define BN      128
#define ASTR    264              // A_s row stride in bf16 (528B = 33*16)
#define CHUNK_K 32
#define NCHUNK  8                // chunks per tile
#define NPHASE  16               // 2 tiles x 8 chunks
#define NBUF    4
#define BSTR    40               // B_s row stride in fp32 (160B = 10*16)
#define BBUF    (BN * BSTR)      // one B buffer, floats (5120)
#define GRID2   125
#define NTILES  (NCLS / BN)      // 250

__device__ __forceinline__ void cp16(void* dst_smem, const void* src) {
    uint32_t d = (uint32_t)__cvta_generic_to_shared(dst_smem);
    asm volatile("cp.async.cg.shared.global [%0], [%1], 16;" :: "r"(d), "l"(src));
}
__device__ __forceinline__ void cp_commit() {
    asm volatile("cp.async.commit_group;" ::: "memory");
}
__device__ __forceinline__ void cp_wait2() {
    asm volatile("cp.async.wait_group 2;" ::: "memory");
}

// Issue one B chunk (CHUNK_K=32 fp32 cols x 128 rows) into buffer `dst`.
__device__ __forceinline__ void issue_b_chunk(
    float* dst, const float* __restrict__ W_w, int n0, int ck, int tid)
{
#pragma unroll
    for (int k = 0; k < 2; k++) {
        int idx = tid + k * 512;           // 1024 segs (128 rows x 8 segs)
        int row = idx >> 3;
        int seg = idx & 7;                 // 8 segs * 16B = 128B = 32 floats
        cp16(dst + row * BSTR + seg * 4,
             W_w + (size_t)(n0 + row) * HID + ck * CHUNK_K + seg * 4);
    }
}

__global__ void __launch_bounds__(512, 1) logits_kernel(
    const float* __restrict__ W_w, const float* __restrict__ b_out,
    float* __restrict__ out)
{
    extern __shared__ char smem_raw[];
    __nv_bfloat16* A_s = (__nv_bfloat16*)smem_raw;              // [256][ASTR]
    float*         B_s = (float*)(smem_raw + BM * ASTR * 2);    // 4*[128][BSTR]

    const int tid = threadIdx.x;
    const int bid = blockIdx.x;
    const int n0_t0 = bid * BN;                 // tile 0
    const int n0_t1 = (bid + GRID2) * BN;       // tile 1

    // --- issue A load once: all of g_h0 (128KB) in 16B segments ---
    {
        const char* src = (const char*)g_h0;
#pragma unroll
        for (int k = 0; k < 16; k++) {
            int idx = tid + k * 512;       // 8192 segs (256 rows x 32 segs)
            int row = idx >> 5;
            int seg = idx & 31;
            cp16((char*)A_s + row * (ASTR * 2) + seg * 16,
                 src + row * (HID * 2) + seg * 16);
        }
    }
    // prologue: chunks 0,1,2 of tile 0 (chunk 0's group includes A)
    issue_b_chunk(B_s + 0 * BBUF, W_w, n0_t0, 0, tid); cp_commit();
    issue_b_chunk(B_s + 1 * BBUF, W_w, n0_t0, 1, tid); cp_commit();
    issue_b_chunk(B_s + 2 * BBUF, W_w, n0_t0, 2, tid); cp_commit();

    const int wid  = tid >> 5;
    const int lane = tid & 31;
    const int wm   = wid >> 2;      // 0..3 -> M offset wm*64
    const int wn   = wid & 3;       // 0..3 -> N offset wn*32
    const int gr   = lane >> 2;
    const int tig  = lane & 3;
    const int lm_row = (lane & 15);
    const int lm_col = ((lane >> 4) & 1) << 3;

    float acc[4][4][4];
#pragma unroll
    for (int mi = 0; mi < 4; mi++)
#pragma unroll
        for (int ni = 0; ni < 4; ni++)
#pragma unroll
            for (int r = 0; r < 4; r++) acc[mi][ni][r] = 0.0f;

#pragma unroll
    for (int g = 0; g < NPHASE; g++) {
        const int c = g & 7;                          // chunk within tile
        cp_wait2();        // group for chunk g (and A at g==0) complete
        __syncthreads();   // single sync: data visible to all; also protects
                           // refill below (target buf consumed 2 phases ago)

        // ---- compute 2 kk steps of chunk g from buf g&3 ----
        const float* Bb = B_s + (g & 3) * BBUF;
#pragma unroll
        for (int kkl = 0; kkl < CHUNK_K / 16; kkl++) {
            const int kbg = c * CHUNK_K + kkl * 16;   // K offset in A
            const int kbl = kkl * 16;                 // K offset in B buf
            uint32_t a[4][4];
#pragma unroll
            for (int mi = 0; mi < 4; mi++) {
                uint32_t addr = (uint32_t)__cvta_generic_to_shared(
                    &A_s[(wm * 64 + mi * 16 + lm_row) * ASTR + kbg + lm_col]);
                asm volatile(
                    "ldmatrix.sync.aligned.m8n8.x4.shared.b16 {%0,%1,%2,%3}, [%4];"
                    : "=r"(a[mi][0]), "=r"(a[mi][1]), "=r"(a[mi][2]), "=r"(a[mi][3])
                    : "r"(addr));
            }
            uint32_t bf[4][2];
#pragma unroll
            for (int ni = 0; ni < 4; ni++) {
                const float* p =
                    Bb + (wn * 32 + ni * 8 + gr) * BSTR + kbl + tig * 2;
                float2 f0 = *(const float2*)(p);
                float2 f1 = *(const float2*)(p + 8);
                __nv_bfloat162 p0 = __floats2bfloat162_rn(f0.x, f0.y);
                __nv_bfloat162 p1 = __floats2bfloat162_rn(f1.x, f1.y);
                bf[ni][0] = *(const uint32_t*)&p0;
                bf[ni][1] = *(const uint32_t*)&p1;
            }
#pragma unroll
            for (int mi = 0; mi < 4; mi++) {
#pragma unroll
                for (int ni = 0; ni < 4; ni++) {
                    asm volatile(
                        "mma.sync.aligned.m16n8k16.row.col.f32.bf16.bf16.f32 "
                        "{%0,%1,%2,%3}, {%4,%5,%6,%7}, {%8,%9}, {%0,%1,%2,%3};"
                        : "+f"(acc[mi][ni][0]), "+f"(acc[mi][ni][1]),
                          "+f"(acc[mi][ni][2]), "+f"(acc[mi][ni][3])
                        : "r"(a[mi][0]), "r"(a[mi][1]), "r"(a[mi][2]), "r"(a[mi][3]),
                          "r"(bf[ni][0]), "r"(bf[ni][1]));
                }
            }
        }

        // ---- issue chunk g+3 (may belong to tile 1) into buf (g+3)&3 ----
        if (g + 3 < NPHASE) {
            int gi  = g + 3;
            int nn0 = (gi < NCHUNK) ? n0_t0 : n0_t1;
            issue_b_chunk(B_s + ((gi) & 3) * BBUF, W_w, nn0, gi & 7, tid);
        }
        cp_commit();       // unconditional: exact group numbering

        // ---- tile epilogue after its last chunk (overlaps next tile's loads)
        if (c == NCHUNK - 1) {
            const int n0 = (g < NCHUNK) ? n0_t0 : n0_t1;
            float bo0[4], bo1[4];
#pragma unroll
            for (int ni = 0; ni < 4; ni++) {
                int col = n0 + wn * 32 + ni * 8 + tig * 2;
                bo0[ni] = b_out[col];
                bo1[ni] = b_out[col + 1];
            }
#pragma unroll
            for (int mi = 0; mi < 4; mi++) {
                int row = wm * 64 + mi * 16 + gr;
#pragma unroll
                for (int ni = 0; ni < 4; ni++) {
                    int col = n0 + wn * 32 + ni * 8 + tig * 2;
                    float2 v0 = make_float2(acc[mi][ni][0] + bo0[ni],
                                            acc[mi][ni][1] + bo1[ni]);
                    float2 v1 = make_float2(acc[mi][ni][2] + bo0[ni],
                                            acc[mi][ni][3] + bo1[ni]);
                    *(float2*)(&out[(size_t)row * NCLS + col])       = v0;
                    *(float2*)(&out[(size_t)(row + 8) * NCLS + col]) = v1;
                }
            }
#pragma unroll
            for (int mi = 0; mi < 4; mi++)
#pragma unroll
                for (int ni = 0; ni < 4; ni++)
#pragma unroll
                    for (int r = 0; r < 4; r++) acc[mi][ni][r] = 0.0f;
        }
    }
}

// ---------------------------------------------------------------------------
// Launcher
// Input order: 0=X 1=C_table 2=U_i 3=V_i 4=b_i 5=U_f 6=V_f 7=b_f
//  8=U_c 9=V_c 10=b_c 11=U_o 12=V_o 13=b_o 14..25=layer1 (unused) 26=W_w 27=b_out
// ---------------------------------------------------------------------------
extern "C" void kernel_launch(void* const* d_in, const int* in_sizes, int n_in,
                              void* d_out, int out_size)
{
    const int*   X       = (const int*)d_in[0];
    const float* C_table = (const float*)d_in[1];
    const float* U_i     = (const float*)d_in[2];
    const float* b_i     = (const float*)d_in[4];
    const float* U_c     = (const float*)d_in[8];
    const float* b_c     = (const float*)d_in[10];
    const float* U_o     = (const float*)d_in[11];
    const float* b_o     = (const float*)d_in[13];
    const float* W_w     = (const float*)d_in[26];
    const float* b_out   = (const float*)d_in[27];
    float* out = (float*)d_out;

    dim3 grid1(4, 32);
    lstm_h0_kernel<<<grid1, 256>>>(X, C_table, U_i, b_i, U_c, b_c, U_o, b_o);

    const int smem_bytes = BM * ASTR * 2 + NBUF * BBUF * (int)sizeof(float); // 217088
    cudaFuncSetAttribute(logits_kernel,
                         cudaFuncAttributeMaxDynamicSharedMemorySize, smem_bytes);
    logits_kernel<<<GRID2, 512, smem_bytes>>>(W_w, b_out, out);
}

// round 12
// speedup vs baseline: 1.3310x; 1.0043x over previous
#include <cuda_runtime.h>
#include <cuda_bf16.h>
#include <cstdint>

// Problem constants (fixed shapes)
#define B_SZ   256
#define T_SZ   512
#define EMB    128
#define HID    256
#define NCLS   32000

// Scratch: h0 at last timestep, stored bf16 for tensor-core GEMM
__device__ __nv_bfloat16 g_h0[B_SZ * HID];

// ---------------------------------------------------------------------------
// Kernel 1: h0_last[b, h] for the 256 last-timestep tokens. (validated)
// ---------------------------------------------------------------------------
__global__ void __launch_bounds__(256) lstm_h0_kernel(
    const int* __restrict__ X, const float* __restrict__ C_table,
    const float* __restrict__ U_i, const float* __restrict__ b_i,
    const float* __restrict__ U_c, const float* __restrict__ b_c,
    const float* __restrict__ U_o, const float* __restrict__ b_o)
{
    __shared__ float E_s[8][EMB];
    const int tid = threadIdx.x;
    const int b0  = blockIdx.y * 8;

    for (int i = tid; i < 8 * EMB; i += 256) {
        int b = i >> 7;
        int e = i & (EMB - 1);
        int tok = X[(b0 + b) * T_SZ + (T_SZ - 1)];
        E_s[b][e] = C_table[tok * EMB + e];
    }
    __syncthreads();

    const int h    = blockIdx.x * 64 + (tid & 63);
    const int bsub = tid >> 6;
    const int r0   = bsub * 2;

    float ai[2], ag[2], ao[2];
    const float bi = b_i[h], bc = b_c[h], bo = b_o[h];
#pragma unroll
    for (int r = 0; r < 2; r++) { ai[r] = bi; ag[r] = bc; ao[r] = bo; }

#pragma unroll 4
    for (int e = 0; e < EMB; e++) {
        float ui = U_i[e * HID + h];
        float uc = U_c[e * HID + h];
        float uo = U_o[e * HID + h];
#pragma unroll
        for (int r = 0; r < 2; r++) {
            float ev = E_s[r0 + r][e];
            ai[r] = fmaf(ev, ui, ai[r]);
            ag[r] = fmaf(ev, uc, ag[r]);
            ao[r] = fmaf(ev, uo, ao[r]);
        }
    }

#pragma unroll
    for (int r = 0; r < 2; r++) {
        float i0 = 1.0f / (1.0f + __expf(-ai[r]));
        float g0 = tanhf(ag[r]);
        float o0 = 1.0f / (1.0f + __expf(-ao[r]));
        float c0 = i0 * g0;
        float h0 = o0 * tanhf(c0);
        g_h0[(b0 + r0 + r) * HID + h] = __float2bfloat16(h0);
    }
}

// ---------------------------------------------------------------------------
// Kernel 2: logits[256, 32000] = h0[256,256] @ W_w[32000,256]^T + b_out
// Balanced persistent bf16 mma.sync GEMM with FOUR decoupled wn-group
// pipelines (named barriers; no CTA-wide sync in the main loop).
//   GRID = 125 CTAs x 512 thr; each CTA does exactly 2 tiles (bid, bid+125).
//   wn-group g (warps {g, g+4, g+8, g+12}, 128 thr) owns B rows
//   [g*32, g*32+32): loads them via cp.async, waits its own groups, and
//   syncs ONLY within the group via bar.sync(1+g, 128).
//   16 flat chunk phases, CHUNK_K=32, 4 buffers, wait_group 2; refill issued
//   BEFORE compute. A (h0) loaded once per CTA, one CTA sync for A.
// ---------------------------------------------------------------------------
#define BM      256
#define BN      128
#define ASTR    264              // A_s row stride in bf16 (528B = 33*16)
#define CHUNK_K 32
#define NCHUNK  8                // chunks per tile
#define NPHASE  16               // 2 tiles x 8 chunks
#define NBUF    4
#define BSTR    40               // B_s row stride in fp32 (160B = 10*16)
#define BBUF    (BN * BSTR)      // one B buffer, floats (5120)
#define GRID2   125
#define NTILES  (NCLS / BN)      // 250

__device__ __forceinline__ void cp16(void* dst_smem, const void* src) {
    uint32_t d = (uint32_t)__cvta_generic_to_shared(dst_smem);
    asm volatile("cp.async.cg.shared.global [%0], [%1], 16;" :: "r"(d), "l"(src));
}
__device__ __forceinline__ void cp_commit() {
    asm volatile("cp.async.commit_group;" ::: "memory");
}
__device__ __forceinline__ void cp_wait2() {
    asm volatile("cp.async.wait_group 2;" ::: "memory");
}
__device__ __forceinline__ void group_bar(int wn) {
    asm volatile("bar.sync %0, 128;" :: "r"(1 + wn) : "memory");
}

// Issue this wn-group's 32 rows of one B chunk into buffer `dst`.
// gidx in [0,128): group-local thread index. 256 segs = 32 rows x 8 segs.
__device__ __forceinline__ void issue_b_rows(
    float* dst, const float* __restrict__ W_w, int n0, int ck,
    int wn, int gidx)
{
#pragma unroll
    for (int k = 0; k < 2; k++) {
        int idx = gidx + k * 128;          // 0..255
        int rl  = idx >> 3;                // local row 0..31
        int seg = idx & 7;                 // 8 segs * 16B = 128B = 32 floats
        int row = wn * 32 + rl;
        cp16(dst + row * BSTR + seg * 4,
             W_w + (size_t)(n0 + row) * HID + ck * CHUNK_K + seg * 4);
    }
}

__global__ void __launch_bounds__(512, 1) logits_kernel(
    const float* __restrict__ W_w, const float* __restrict__ b_out,
    float* __restrict__ out)
{
    extern __shared__ char smem_raw[];
    __nv_bfloat16* A_s = (__nv_bfloat16*)smem_raw;              // [256][ASTR]
    float*         B_s = (float*)(smem_raw + BM * ASTR * 2);    // 4*[128][BSTR]

    const int tid = threadIdx.x;
    const int bid = blockIdx.x;
    const int n0_t0 = bid * BN;                 // tile 0
    const int n0_t1 = (bid + GRID2) * BN;       // tile 1

    const int wid  = tid >> 5;
    const int lane = tid & 31;
    const int wm   = wid >> 2;      // 0..3 -> M offset wm*64
    const int wn   = wid & 3;       // 0..3 -> N offset wn*32 (B row group)
    const int gidx = wm * 32 + lane;           // group-local index 0..127
    const int gr   = lane >> 2;
    const int tig  = lane & 3;
    const int lm_row = (lane & 15);
    const int lm_col = ((lane >> 4) & 1) << 3;

    // --- group 0: A load (every thread contributes its 16 segs) ---
    {
        const char* src = (const char*)g_h0;
#pragma unroll
        for (int k = 0; k < 16; k++) {
            int idx = tid + k * 512;       // 8192 segs (256 rows x 32 segs)
            int row = idx >> 5;
            int seg = idx & 31;
            cp16((char*)A_s + row * (ASTR * 2) + seg * 16,
                 src + row * (HID * 2) + seg * 16);
        }
    }
    cp_commit();                                           // group 0: A
    // --- groups 1..3: this wn-group's rows of chunks 0,1,2 (tile 0) ---
    issue_b_rows(B_s + 0 * BBUF, W_w, n0_t0, 0, wn, gidx); cp_commit();
    issue_b_rows(B_s + 1 * BBUF, W_w, n0_t0, 1, wn, gidx); cp_commit();
    issue_b_rows(B_s + 2 * BBUF, W_w, n0_t0, 2, wn, gidx); cp_commit();

    // One-time CTA sync: A (group 0) + chunk 0 (group 1) complete per thread,
    // then CTA barrier makes A visible to all warps.
    cp_wait2();
    __syncthreads();

    float acc[4][4][4];
#pragma unroll
    for (int mi = 0; mi < 4; mi++)
#pragma unroll
        for (int ni = 0; ni < 4; ni++)
#pragma unroll
            for (int r = 0; r < 4; r++) acc[mi][ni][r] = 0.0f;

#pragma unroll
    for (int g = 0; g < NPHASE; g++) {
        const int c = g & 7;                          // chunk within tile
        cp_wait2();          // own groups: chunk g resident (A at g==0 too)
        group_bar(wn);       // group-wide: all 128 threads' chunk-g loads done

        // ---- issue chunk g+3 (own rows) BEFORE compute; buf (g+3)&3 was
        //      last read in compute g-1, and every group thread passed this
        //      phase's bar only after finishing compute g-1 -> safe.
        if (g + 3 < NPHASE) {
            int gi  = g + 3;
            int nn0 = (gi < NCHUNK) ? n0_t0 : n0_t1;
            issue_b_rows(B_s + (gi & 3) * BBUF, W_w, nn0, gi & 7, wn, gidx);
        }
        cp_commit();         // unconditional: exact group numbering

        // ---- compute 2 kk steps of chunk g from buf g&3 ----
        const float* Bb = B_s + (g & 3) * BBUF;
#pragma unroll
        for (int kkl = 0; kkl < CHUNK_K / 16; kkl++) {
            const int kbg = c * CHUNK_K + kkl * 16;   // K offset in A
            const int kbl = kkl * 16;                 // K offset in B buf
            uint32_t a[4][4];
#pragma unroll
            for (int mi = 0; mi < 4; mi++) {
                uint32_t addr = (uint32_t)__cvta_generic_to_shared(
                    &A_s[(wm * 64 + mi * 16 + lm_row) * ASTR + kbg + lm_col]);
                asm volatile(
                    "ldmatrix.sync.aligned.m8n8.x4.shared.b16 {%0,%1,%2,%3}, [%4];"
                    : "=r"(a[mi][0]), "=r"(a[mi][1]), "=r"(a[mi][2]), "=r"(a[mi][3])
                    : "r"(addr));
            }
            uint32_t bf[4][2];
#pragma unroll
            for (int ni = 0; ni < 4; ni++) {
                const float* p =
                    Bb + (wn * 32 + ni * 8 + gr) * BSTR + kbl + tig * 2;
                float2 f0 = *(const float2*)(p);
                float2 f1 = *(const float2*)(p + 8);
                __nv_bfloat162 p0 = __floats2bfloat162_rn(f0.x, f0.y);
                __nv_bfloat162 p1 = __floats2bfloat162_rn(f1.x, f1.y);
                bf[ni][0] = *(const uint32_t*)&p0;
                bf[ni][1] = *(const uint32_t*)&p1;
            }
#pragma unroll
            for (int mi = 0; mi < 4; mi++) {
#pragma unroll
                for (int ni = 0; ni < 4; ni++) {
                    asm volatile(
                        "mma.sync.aligned.m16n8k16.row.col.f32.bf16.bf16.f32 "
                        "{%0,%1,%2,%3}, {%4,%5,%6,%7}, {%8,%9}, {%0,%1,%2,%3};"
                        : "+f"(acc[mi][ni][0]), "+f"(acc[mi][ni][1]),
                          "+f"(acc[mi][ni][2]), "+f"(acc[mi][ni][3])
                        : "r"(a[mi][0]), "r"(a[mi][1]), "r"(a[mi][2]), "r"(a[mi][3]),
                          "r"(bf[ni][0]), "r"(bf[ni][1]));
                }
            }
        }

        // ---- tile epilogue after its last chunk (warp-local; no sync) ----
        if (c == NCHUNK - 1) {
            const int n0 = (g < NCHUNK) ? n0_t0 : n0_t1;
            float bo0[4], bo1[4];
#pragma unroll
            for (int ni = 0; ni < 4; ni++) {
                int col = n0 + wn * 32 + ni * 8 + tig * 2;
                bo0[ni] = b_out[col];
                bo1[ni] = b_out[col + 1];
            }
#pragma unroll
            for (int mi = 0; mi < 4; mi++) {
                int row = wm * 64 + mi * 16 + gr;
#pragma unroll
                for (int ni = 0; ni < 4; ni++) {
                    int col = n0 + wn * 32 + ni * 8 + tig * 2;
                    float2 v0 = make_float2(acc[mi][ni][0] + bo0[ni],
                                            acc[mi][ni][1] + bo1[ni]);
                    float2 v1 = make_float2(acc[mi][ni][2] + bo0[ni],
                                            acc[mi][ni][3] + bo1[ni]);
                    *(float2*)(&out[(size_t)row * NCLS + col])       = v0;
                    *(float2*)(&out[(size_t)(row + 8) * NCLS + col]) = v1;
                }
            }
#pragma unroll
            for (int mi = 0; mi < 4; mi++)
#pragma unroll
                for (int ni = 0; ni < 4; ni++)
#pragma unroll
                    for (int r = 0; r < 4; r++) acc[mi][ni][r] = 0.0f;
        }
    }
}

// ---------------------------------------------------------------------------
// Launcher
// Input order: 0=X 1=C_table 2=U_i 3=V_i 4=b_i 5=U_f 6=V_f 7=b_f
//  8=U_c 9=V_c 10=b_c 11=U_o 12=V_o 13=b_o 14..25=layer1 (unused) 26=W_w 27=b_out
// ---------------------------------------------------------------------------
extern "C" void kernel_launch(void* const* d_in, const int* in_sizes, int n_in,
                              void* d_out, int out_size)
{
    const int*   X       = (const int*)d_in[0];
    const float* C_table = (const float*)d_in[1];
    const float* U_i     = (const float*)d_in[2];
    const float* b_i     = (const float*)d_in[4];
    const float* U_c     = (const float*)d_in[8];
    const float* b_c     = (const float*)d_in[10];
    const float* U_o     = (const float*)d_in[11];
    const float* b_o     = (const float*)d_in[13];
    const float* W_w     = (const float*)d_in[26];
    const float* b_out   = (const float*)d_in[27];
    float* out = (float*)d_out;

    dim3 grid1(4, 32);
    lstm_h0_kernel<<<grid1, 256>>>(X, C_table, U_i, b_i, U_c, b_c, U_o, b_o);

    const int smem_bytes = BM * ASTR * 2 + NBUF * BBUF * (int)sizeof(float); // 217088
    cudaFuncSetAttribute(logits_kernel,
                         cudaFuncAttributeMaxDynamicSharedMemorySize, smem_bytes);
    logits_kernel<<<GRID2, 512, smem_bytes>>>(W_w, b_out, out);
}